// round 2
// baseline (speedup 1.0000x reference)
#include <cuda_runtime.h>

#define NN 100000   // nodes
#define HD 128      // hidden dim (= IN = OUT)
#define NR 8        // relations
#define NE 75000    // edges per relation

// Scratch (allocation-free rule: device globals)
__device__ float g_h[(size_t)NN * HD];       // 51.2 MB
__device__ float g_relout[(size_t)NN * HD];  // 51.2 MB

// ---------------------------------------------------------------------------
// Zero rel_out accumulator. grid*block*4 floats == NN*HD exactly (12.8M).
// ---------------------------------------------------------------------------
__global__ void k_zero() {
    size_t i = (size_t)blockIdx.x * blockDim.x + threadIdx.x;
    ((float4*)g_relout)[i] = make_float4(0.f, 0.f, 0.f, 0.f);
}

// ---------------------------------------------------------------------------
// Kernel 1: h = relu(x @ W_in + b_in)
// Tile: 64 rows x 128 cols, K=128. W fully staged in smem (64KB), A tile 32KB.
// 256 threads: warp w owns rows w*8..w*8+7, lane owns cols 4*lane..4*lane+3.
// ---------------------------------------------------------------------------
__global__ void k_in_gemm(const float* __restrict__ x,
                          const float* __restrict__ W,
                          const float* __restrict__ b) {
    extern __shared__ float smem[];
    float* sW = smem;              // 128*128
    float* sA = smem + 128 * 128;  // 64*128
    const int tid = threadIdx.x;

    for (int i = tid; i < 128 * 128 / 4; i += 256)
        ((float4*)sW)[i] = ((const float4*)W)[i];

    const int row0 = blockIdx.x * 64;
    for (int i = tid; i < 64 * 128 / 4; i += 256) {
        int r = i >> 5, c = i & 31;
        int row = row0 + r;
        ((float4*)sA)[i] = (row < NN) ? ((const float4*)(x + (size_t)row * HD))[c]
                                      : make_float4(0.f, 0.f, 0.f, 0.f);
    }
    __syncthreads();

    const int lane = tid & 31, warp = tid >> 5;
    float acc[8][4];
#pragma unroll
    for (int m = 0; m < 8; m++)
        acc[m][0] = acc[m][1] = acc[m][2] = acc[m][3] = 0.f;

    const float* a0 = sA + warp * 8 * 128;
#pragma unroll 4
    for (int k = 0; k < 128; k++) {
        float4 bv = ((float4*)sW)[k * 32 + lane];
#pragma unroll
        for (int m = 0; m < 8; m++) {
            float a = a0[m * 128 + k];
            acc[m][0] += a * bv.x; acc[m][1] += a * bv.y;
            acc[m][2] += a * bv.z; acc[m][3] += a * bv.w;
        }
    }

    float4 bias = ((const float4*)b)[lane];
#pragma unroll
    for (int m = 0; m < 8; m++) {
        int row = row0 + warp * 8 + m;
        if (row < NN) {
            float4 o;
            o.x = fmaxf(acc[m][0] + bias.x, 0.f);
            o.y = fmaxf(acc[m][1] + bias.y, 0.f);
            o.z = fmaxf(acc[m][2] + bias.z, 0.f);
            o.w = fmaxf(acc[m][3] + bias.w, 0.f);
            ((float4*)(g_h + (size_t)row * HD))[lane] = o;
        }
    }
}

// ---------------------------------------------------------------------------
// Kernel 2: per-relation gather -> (w*h[src]) @ W_rel[r] -> atomic scatter.
// grid = (ceil(NE/64), NR). Same 64x128 GEMM structure; A rows are gathered
// edge features (pre-scaled by w). Padding edges use w=0, dst=0 (adds 0.0).
// ---------------------------------------------------------------------------
__global__ void k_rel(const int* __restrict__ esrc,
                      const int* __restrict__ edst,
                      const float* __restrict__ ew,
                      const float* __restrict__ Wrel) {
    extern __shared__ float smem[];
    float* sW = smem;
    float* sA = smem + 128 * 128;
    __shared__ int sDst[64];

    const int r = blockIdx.y;
    const int tid = threadIdx.x;
    const float* Wr = Wrel + (size_t)r * 128 * 128;

    for (int i = tid; i < 128 * 128 / 4; i += 256)
        ((float4*)sW)[i] = ((const float4*)Wr)[i];

    const int e0 = blockIdx.x * 64;
    const int* srcR = esrc + (size_t)r * NE;
    const int* dstR = edst + (size_t)r * NE;
    const float* wR = ew + (size_t)r * NE;

    if (tid < 64) {
        int e = e0 + tid;
        sDst[tid] = (e < NE) ? dstR[e] : 0;
    }
    {
        // 4 threads per edge slot: gather h[src] row (128 floats), scale by w
        int s = tid >> 2, p = tid & 3;
        int e = e0 + s;
        int sidx = 0;
        float we = 0.f;
        if (e < NE) { sidx = srcR[e]; we = wR[e]; }
        const float4* hp = (const float4*)(g_h + (size_t)sidx * HD) + p * 8;
        float4* ap = (float4*)(sA + s * 128) + p * 8;
#pragma unroll
        for (int i = 0; i < 8; i++) {
            float4 v = hp[i];
            v.x *= we; v.y *= we; v.z *= we; v.w *= we;
            ap[i] = v;
        }
    }
    __syncthreads();

    const int lane = tid & 31, warp = tid >> 5;
    float acc[8][4];
#pragma unroll
    for (int m = 0; m < 8; m++)
        acc[m][0] = acc[m][1] = acc[m][2] = acc[m][3] = 0.f;

    const float* a0 = sA + warp * 8 * 128;
#pragma unroll 4
    for (int k = 0; k < 128; k++) {
        float4 bv = ((float4*)sW)[k * 32 + lane];
#pragma unroll
        for (int m = 0; m < 8; m++) {
            float a = a0[m * 128 + k];
            acc[m][0] += a * bv.x; acc[m][1] += a * bv.y;
            acc[m][2] += a * bv.z; acc[m][3] += a * bv.w;
        }
    }

#pragma unroll
    for (int m = 0; m < 8; m++) {
        int d = sDst[warp * 8 + m];
        float* op = g_relout + (size_t)d * HD + lane * 4;
        atomicAdd(op + 0, acc[m][0]);
        atomicAdd(op + 1, acc[m][1]);
        atomicAdd(op + 2, acc[m][2]);
        atomicAdd(op + 3, acc[m][3]);
    }
}

// ---------------------------------------------------------------------------
// Kernel 3 (fused): h2 = relu(h @ W_self + b_self + rel_out); out = h2 @ W_out + b_out
// h2 lives only in registers/smem (saves 102MB HBM traffic).
// Smem: W_self(64K) + W_out(64K) + tile(32K) = 160KB.
// ---------------------------------------------------------------------------
__global__ void k_out(const float* __restrict__ Wself,
                      const float* __restrict__ bself,
                      const float* __restrict__ Wout,
                      const float* __restrict__ bout,
                      float* __restrict__ out) {
    extern __shared__ float smem[];
    float* sW1 = smem;           // W_self
    float* sW2 = smem + 16384;   // W_out
    float* sA  = smem + 32768;   // 64x128 tile (h, then reused for h2)
    const int tid = threadIdx.x;

    for (int i = tid; i < 4096; i += 256)
        ((float4*)sW1)[i] = ((const float4*)Wself)[i];
    for (int i = tid; i < 4096; i += 256)
        ((float4*)sW2)[i] = ((const float4*)Wout)[i];

    const int row0 = blockIdx.x * 64;
    for (int i = tid; i < 2048; i += 256) {
        int r = i >> 5, c = i & 31;
        int row = row0 + r;
        ((float4*)sA)[i] = (row < NN) ? ((const float4*)(g_h + (size_t)row * HD))[c]
                                      : make_float4(0.f, 0.f, 0.f, 0.f);
    }
    __syncthreads();

    const int lane = tid & 31, warp = tid >> 5;
    float acc[8][4];
#pragma unroll
    for (int m = 0; m < 8; m++)
        acc[m][0] = acc[m][1] = acc[m][2] = acc[m][3] = 0.f;

    const float* a0 = sA + warp * 8 * 128;
#pragma unroll 4
    for (int k = 0; k < 128; k++) {
        float4 bv = ((float4*)sW1)[k * 32 + lane];
#pragma unroll
        for (int m = 0; m < 8; m++) {
            float a = a0[m * 128 + k];
            acc[m][0] += a * bv.x; acc[m][1] += a * bv.y;
            acc[m][2] += a * bv.z; acc[m][3] += a * bv.w;
        }
    }

    // epilogue 1: + b_self + rel_out, relu -> h2 (store back into sA)
    float4 bs = ((const float4*)bself)[lane];
    float h2[8][4];
#pragma unroll
    for (int m = 0; m < 8; m++) {
        int row = row0 + warp * 8 + m;
        float4 ro = (row < NN) ? ((const float4*)(g_relout + (size_t)row * HD))[lane]
                               : make_float4(0.f, 0.f, 0.f, 0.f);
        h2[m][0] = fmaxf(acc[m][0] + bs.x + ro.x, 0.f);
        h2[m][1] = fmaxf(acc[m][1] + bs.y + ro.y, 0.f);
        h2[m][2] = fmaxf(acc[m][2] + bs.z + ro.z, 0.f);
        h2[m][3] = fmaxf(acc[m][3] + bs.w + ro.w, 0.f);
    }
    __syncthreads();  // everyone done reading sA as h
#pragma unroll
    for (int m = 0; m < 8; m++) {
        float4 v = make_float4(h2[m][0], h2[m][1], h2[m][2], h2[m][3]);
        ((float4*)(sA + (warp * 8 + m) * 128))[lane] = v;
    }
    __syncthreads();

    // GEMM 2: out = h2 @ W_out + b_out
#pragma unroll
    for (int m = 0; m < 8; m++)
        acc[m][0] = acc[m][1] = acc[m][2] = acc[m][3] = 0.f;
#pragma unroll 4
    for (int k = 0; k < 128; k++) {
        float4 bv = ((float4*)sW2)[k * 32 + lane];
#pragma unroll
        for (int m = 0; m < 8; m++) {
            float a = a0[m * 128 + k];
            acc[m][0] += a * bv.x; acc[m][1] += a * bv.y;
            acc[m][2] += a * bv.z; acc[m][3] += a * bv.w;
        }
    }
    float4 bo = ((const float4*)bout)[lane];
#pragma unroll
    for (int m = 0; m < 8; m++) {
        int row = row0 + warp * 8 + m;
        if (row < NN) {
            float4 o;
            o.x = acc[m][0] + bo.x;
            o.y = acc[m][1] + bo.y;
            o.z = acc[m][2] + bo.z;
            o.w = acc[m][3] + bo.w;
            ((float4*)(out + (size_t)row * HD))[lane] = o;
        }
    }
}

// ---------------------------------------------------------------------------
extern "C" void kernel_launch(void* const* d_in, const int* in_sizes, int n_in,
                              void* d_out, int out_size) {
    const float* x      = (const float*)d_in[0];
    const int*   esrc   = (const int*)d_in[1];
    const int*   edst   = (const int*)d_in[2];
    const float* ew     = (const float*)d_in[3];
    const float* W_in   = (const float*)d_in[4];
    const float* b_in   = (const float*)d_in[5];
    const float* W_rel  = (const float*)d_in[6];
    const float* W_self = (const float*)d_in[7];
    const float* b_self = (const float*)d_in[8];
    const float* W_out  = (const float*)d_in[9];
    const float* b_out  = (const float*)d_in[10];
    float* out = (float*)d_out;

    const int SMEM_GEMM = (128 * 128 + 64 * 128) * 4;           // 98304
    const int SMEM_OUT  = (2 * 128 * 128 + 64 * 128) * 4;       // 163840

    // One-time (first call is the non-captured correctness run); keeps the
    // capture call launches-only.
    static bool s_attr_done = false;
    if (!s_attr_done) {
        cudaFuncSetAttribute(k_in_gemm, cudaFuncAttributeMaxDynamicSharedMemorySize, SMEM_GEMM);
        cudaFuncSetAttribute(k_rel,     cudaFuncAttributeMaxDynamicSharedMemorySize, SMEM_GEMM);
        cudaFuncSetAttribute(k_out,     cudaFuncAttributeMaxDynamicSharedMemorySize, SMEM_OUT);
        s_attr_done = true;
    }

    // 1) zero rel_out (12.8M floats = 12500 * 256 * 4)
    k_zero<<<12500, 256>>>();

    // 2) h = relu(x @ W_in + b_in)
    k_in_gemm<<<(NN + 63) / 64, 256, SMEM_GEMM>>>(x, W_in, b_in);

    // 3) rel_out += per-edge transform-scatter over all relations
    dim3 grel((NE + 63) / 64, NR);
    k_rel<<<grel, 256, SMEM_GEMM>>>(esrc, edst, ew, W_rel);

    // 4) fused: relu(h @ W_self + b_self + rel_out) @ W_out + b_out
    k_out<<<(NN + 63) / 64, 256, SMEM_OUT>>>(W_self, b_self, W_out, b_out, out);
}

// round 3
// speedup vs baseline: 1.2399x; 1.2399x over previous
#include <cuda_runtime.h>

#define NN 100000   // nodes
#define HD 128      // hidden dim (= IN = OUT)
#define NR 8        // relations
#define NE 75000    // edges per relation

// Scratch (allocation-free rule: device globals)
__device__ float g_h[(size_t)NN * HD];       // 51.2 MB
__device__ float g_h2[(size_t)NN * HD];      // 51.2 MB
__device__ float g_relout[(size_t)NN * HD];  // 51.2 MB

// ---------------------------------------------------------------------------
// Zero rel_out accumulator. grid*block*1 float4 == NN*HD/4 exactly (3.2M).
// ---------------------------------------------------------------------------
__global__ void k_zero() {
    size_t i = (size_t)blockIdx.x * blockDim.x + threadIdx.x;
    ((float4*)g_relout)[i] = make_float4(0.f, 0.f, 0.f, 0.f);
}

// ---------------------------------------------------------------------------
// Vectorized 64x128x128 GEMM microkernel.
// sW: [128][128] weights (row k, col n). sA: [64][128] activations.
// Warp w owns rows w*8..w*8+7; lane owns cols 4*lane..4*lane+3.
// k-loop vectorized by 4: per k4 -> 4 B-vector LDS.128 + 8 broadcast A LDS.128
// + 128 FFMA per thread.
// ---------------------------------------------------------------------------
__device__ __forceinline__ void gemm_tile_64x128(const float* __restrict__ sW,
                                                 const float* __restrict__ sA,
                                                 int lane, int warp,
                                                 float4 acc[8]) {
    const float4* sW4 = (const float4*)sW;
    const float4* a4 = (const float4*)(sA + warp * 8 * 128);
#pragma unroll
    for (int m = 0; m < 8; m++) acc[m] = make_float4(0.f, 0.f, 0.f, 0.f);

#pragma unroll 4
    for (int k4 = 0; k4 < 32; k4++) {
        float4 b0 = sW4[(4 * k4 + 0) * 32 + lane];
        float4 b1 = sW4[(4 * k4 + 1) * 32 + lane];
        float4 b2 = sW4[(4 * k4 + 2) * 32 + lane];
        float4 b3 = sW4[(4 * k4 + 3) * 32 + lane];
#pragma unroll
        for (int m = 0; m < 8; m++) {
            float4 av = a4[m * 32 + k4];
            acc[m].x += av.x * b0.x; acc[m].y += av.x * b0.y;
            acc[m].z += av.x * b0.z; acc[m].w += av.x * b0.w;
            acc[m].x += av.y * b1.x; acc[m].y += av.y * b1.y;
            acc[m].z += av.y * b1.z; acc[m].w += av.y * b1.w;
            acc[m].x += av.z * b2.x; acc[m].y += av.z * b2.y;
            acc[m].z += av.z * b2.z; acc[m].w += av.z * b2.w;
            acc[m].x += av.w * b3.x; acc[m].y += av.w * b3.y;
            acc[m].z += av.w * b3.z; acc[m].w += av.w * b3.w;
        }
    }
}

// ---------------------------------------------------------------------------
// Kernel 1: h = relu(x @ W_in + b_in).  96KB smem -> 2 CTAs/SM.
// ---------------------------------------------------------------------------
__global__ void __launch_bounds__(256, 2)
k_in_gemm(const float* __restrict__ x,
          const float* __restrict__ W,
          const float* __restrict__ b) {
    extern __shared__ float smem[];
    float* sW = smem;              // 128*128
    float* sA = smem + 128 * 128;  // 64*128
    const int tid = threadIdx.x;

    for (int i = tid; i < 4096; i += 256)
        ((float4*)sW)[i] = ((const float4*)W)[i];

    const int row0 = blockIdx.x * 64;
    for (int i = tid; i < 2048; i += 256) {
        int r = i >> 5, c = i & 31;
        int row = row0 + r;
        ((float4*)sA)[i] = (row < NN) ? ((const float4*)(x + (size_t)row * HD))[c]
                                      : make_float4(0.f, 0.f, 0.f, 0.f);
    }
    __syncthreads();

    const int lane = tid & 31, warp = tid >> 5;
    float4 acc[8];
    gemm_tile_64x128(sW, sA, lane, warp, acc);

    float4 bias = ((const float4*)b)[lane];
#pragma unroll
    for (int m = 0; m < 8; m++) {
        int row = row0 + warp * 8 + m;
        if (row < NN) {
            float4 o;
            o.x = fmaxf(acc[m].x + bias.x, 0.f);
            o.y = fmaxf(acc[m].y + bias.y, 0.f);
            o.z = fmaxf(acc[m].z + bias.z, 0.f);
            o.w = fmaxf(acc[m].w + bias.w, 0.f);
            ((float4*)(g_h + (size_t)row * HD))[lane] = o;
        }
    }
}

// ---------------------------------------------------------------------------
// Kernel 2: per-relation gather -> (w*h[src]) @ W_rel[r] -> vector red scatter.
// grid = (ceil(NE/64), NR). Padding edges: w=0, dst=0 (adds exactly 0.0).
// ---------------------------------------------------------------------------
__global__ void __launch_bounds__(256, 2)
k_rel(const int* __restrict__ esrc,
      const int* __restrict__ edst,
      const float* __restrict__ ew,
      const float* __restrict__ Wrel) {
    extern __shared__ float smem[];
    float* sW = smem;
    float* sA = smem + 128 * 128;
    __shared__ int sDst[64];

    const int r = blockIdx.y;
    const int tid = threadIdx.x;
    const float* Wr = Wrel + (size_t)r * 128 * 128;

    for (int i = tid; i < 4096; i += 256)
        ((float4*)sW)[i] = ((const float4*)Wr)[i];

    const int e0 = blockIdx.x * 64;
    const int* srcR = esrc + (size_t)r * NE;
    const int* dstR = edst + (size_t)r * NE;
    const float* wR = ew + (size_t)r * NE;

    if (tid < 64) {
        int e = e0 + tid;
        sDst[tid] = (e < NE) ? dstR[e] : 0;
    }
    {
        // 4 threads per edge slot: gather h[src] row (128 floats), scale by w
        int s = tid >> 2, p = tid & 3;
        int e = e0 + s;
        int sidx = 0;
        float we = 0.f;
        if (e < NE) { sidx = srcR[e]; we = wR[e]; }
        const float4* hp = (const float4*)(g_h + (size_t)sidx * HD) + p * 8;
        float4* ap = (float4*)(sA + s * 128) + p * 8;
#pragma unroll
        for (int i = 0; i < 8; i++) {
            float4 v = hp[i];
            v.x *= we; v.y *= we; v.z *= we; v.w *= we;
            ap[i] = v;
        }
    }
    __syncthreads();

    const int lane = tid & 31, warp = tid >> 5;
    float4 acc[8];
    gemm_tile_64x128(sW, sA, lane, warp, acc);

#pragma unroll
    for (int m = 0; m < 8; m++) {
        int d = sDst[warp * 8 + m];
        float* op = g_relout + (size_t)d * HD + lane * 4;
        asm volatile("red.global.add.v4.f32 [%0], {%1, %2, %3, %4};"
                     :: "l"(op), "f"(acc[m].x), "f"(acc[m].y),
                        "f"(acc[m].z), "f"(acc[m].w)
                     : "memory");
    }
}

// ---------------------------------------------------------------------------
// Kernel 3: h2 = relu(h @ W_self + b_self + rel_out)
// ---------------------------------------------------------------------------
__global__ void __launch_bounds__(256, 2)
k_self(const float* __restrict__ Wself,
       const float* __restrict__ bself) {
    extern __shared__ float smem[];
    float* sW = smem;
    float* sA = smem + 128 * 128;
    const int tid = threadIdx.x;

    for (int i = tid; i < 4096; i += 256)
        ((float4*)sW)[i] = ((const float4*)Wself)[i];

    const int row0 = blockIdx.x * 64;
    for (int i = tid; i < 2048; i += 256) {
        int r = i >> 5, c = i & 31;
        int row = row0 + r;
        ((float4*)sA)[i] = (row < NN) ? ((const float4*)(g_h + (size_t)row * HD))[c]
                                      : make_float4(0.f, 0.f, 0.f, 0.f);
    }
    __syncthreads();

    const int lane = tid & 31, warp = tid >> 5;
    float4 acc[8];
    gemm_tile_64x128(sW, sA, lane, warp, acc);

    float4 bs = ((const float4*)bself)[lane];
#pragma unroll
    for (int m = 0; m < 8; m++) {
        int row = row0 + warp * 8 + m;
        if (row < NN) {
            float4 ro = ((const float4*)(g_relout + (size_t)row * HD))[lane];
            float4 o;
            o.x = fmaxf(acc[m].x + bs.x + ro.x, 0.f);
            o.y = fmaxf(acc[m].y + bs.y + ro.y, 0.f);
            o.z = fmaxf(acc[m].z + bs.z + ro.z, 0.f);
            o.w = fmaxf(acc[m].w + bs.w + ro.w, 0.f);
            ((float4*)(g_h2 + (size_t)row * HD))[lane] = o;
        }
    }
}

// ---------------------------------------------------------------------------
// Kernel 4: out = h2 @ W_out + b_out
// ---------------------------------------------------------------------------
__global__ void __launch_bounds__(256, 2)
k_out2(const float* __restrict__ Wout,
       const float* __restrict__ bout,
       float* __restrict__ out) {
    extern __shared__ float smem[];
    float* sW = smem;
    float* sA = smem + 128 * 128;
    const int tid = threadIdx.x;

    for (int i = tid; i < 4096; i += 256)
        ((float4*)sW)[i] = ((const float4*)Wout)[i];

    const int row0 = blockIdx.x * 64;
    for (int i = tid; i < 2048; i += 256) {
        int r = i >> 5, c = i & 31;
        int row = row0 + r;
        ((float4*)sA)[i] = (row < NN) ? ((const float4*)(g_h2 + (size_t)row * HD))[c]
                                      : make_float4(0.f, 0.f, 0.f, 0.f);
    }
    __syncthreads();

    const int lane = tid & 31, warp = tid >> 5;
    float4 acc[8];
    gemm_tile_64x128(sW, sA, lane, warp, acc);

    float4 bo = ((const float4*)bout)[lane];
#pragma unroll
    for (int m = 0; m < 8; m++) {
        int row = row0 + warp * 8 + m;
        if (row < NN) {
            float4 o;
            o.x = acc[m].x + bo.x;
            o.y = acc[m].y + bo.y;
            o.z = acc[m].z + bo.z;
            o.w = acc[m].w + bo.w;
            ((float4*)(out + (size_t)row * HD))[lane] = o;
        }
    }
}

// ---------------------------------------------------------------------------
extern "C" void kernel_launch(void* const* d_in, const int* in_sizes, int n_in,
                              void* d_out, int out_size) {
    const float* x      = (const float*)d_in[0];
    const int*   esrc   = (const int*)d_in[1];
    const int*   edst   = (const int*)d_in[2];
    const float* ew     = (const float*)d_in[3];
    const float* W_in   = (const float*)d_in[4];
    const float* b_in   = (const float*)d_in[5];
    const float* W_rel  = (const float*)d_in[6];
    const float* W_self = (const float*)d_in[7];
    const float* b_self = (const float*)d_in[8];
    const float* W_out  = (const float*)d_in[9];
    const float* b_out  = (const float*)d_in[10];
    float* out = (float*)d_out;

    const int SMEM_GEMM = (128 * 128 + 64 * 128) * 4;  // 98304

    static bool s_attr_done = false;
    if (!s_attr_done) {
        cudaFuncSetAttribute(k_in_gemm, cudaFuncAttributeMaxDynamicSharedMemorySize, SMEM_GEMM);
        cudaFuncSetAttribute(k_rel,     cudaFuncAttributeMaxDynamicSharedMemorySize, SMEM_GEMM);
        cudaFuncSetAttribute(k_self,    cudaFuncAttributeMaxDynamicSharedMemorySize, SMEM_GEMM);
        cudaFuncSetAttribute(k_out2,    cudaFuncAttributeMaxDynamicSharedMemorySize, SMEM_GEMM);
        s_attr_done = true;
    }

    // 1) zero rel_out
    k_zero<<<12500, 256>>>();

    // 2) h = relu(x @ W_in + b_in)
    k_in_gemm<<<(NN + 63) / 64, 256, SMEM_GEMM>>>(x, W_in, b_in);

    // 3) rel_out += per-edge transform-scatter over all relations
    dim3 grel((NE + 63) / 64, NR);
    k_rel<<<grel, 256, SMEM_GEMM>>>(esrc, edst, ew, W_rel);

    // 4) h2 = relu(h @ W_self + b_self + rel_out)
    k_self<<<(NN + 63) / 64, 256, SMEM_GEMM>>>(W_self, b_self);

    // 5) out = h2 @ W_out + b_out
    k_out2<<<(NN + 63) / 64, 256, SMEM_GEMM>>>(W_out, b_out, out);
}

// round 6
// speedup vs baseline: 1.6862x; 1.3599x over previous
#include <cuda_runtime.h>
#include <cuda_bf16.h>
#include <cstdint>

#define NN 100000   // nodes
#define HD 128      // hidden dim (= IN = OUT)
#define NR 8        // relations
#define NE 75000    // edges per relation
#define KP 136      // padded K stride (bf16 elems) for conflict-free fragment loads

// Scratch (allocation-free rule: device globals)
__device__ float g_h[(size_t)NN * HD];        // 51.2 MB
__device__ float g_h2[(size_t)NN * HD];       // 51.2 MB
__device__ float g_relout[(size_t)NN * HD];   // 51.2 MB
// Pre-split transposed weights B[n][k] (k-stride KP), bf16 hi/lo.
// Slot: 0=W_in, 1..8=W_rel[r], 9=W_self, 10=W_out.
__device__ __nv_bfloat16 g_whi[11 * 128 * KP];
__device__ __nv_bfloat16 g_wlo[11 * 128 * KP];

// m16n8k16 bf16 MMA, fp32 accumulate (baseline PTX, works on plain sm_100)
#define MMA16816(c, a0, a1, a2, a3, b0, b1) \
    asm volatile("mma.sync.aligned.m16n8k16.row.col.f32.bf16.bf16.f32 " \
                 "{%0,%1,%2,%3}, {%4,%5,%6,%7}, {%8,%9}, {%0,%1,%2,%3};" \
                 : "+f"((c)[0]), "+f"((c)[1]), "+f"((c)[2]), "+f"((c)[3]) \
                 : "r"(a0), "r"(a1), "r"(a2), "r"(a3), "r"(b0), "r"(b1))

// split two floats into packed bf16x2 hi and lo (lo = v - bf16(v))
__device__ __forceinline__ void split2(float a, float b, uint32_t& h, uint32_t& l) {
    __nv_bfloat16 ha = __float2bfloat16_rn(a);
    __nv_bfloat16 hb = __float2bfloat16_rn(b);
    __nv_bfloat162 hp; hp.x = ha; hp.y = hb;
    __nv_bfloat162 lp = __floats2bfloat162_rn(a - __bfloat162float(ha),
                                              b - __bfloat162float(hb));
    h = *reinterpret_cast<uint32_t*>(&hp);
    l = *reinterpret_cast<uint32_t*>(&lp);
}

// ---------------------------------------------------------------------------
// k_zero: zero rel_out (12.8M floats)
// ---------------------------------------------------------------------------
__global__ void k_zero() {
    size_t i = (size_t)blockIdx.x * blockDim.x + threadIdx.x;
    ((float4*)g_relout)[i] = make_float4(0.f, 0.f, 0.f, 0.f);
}

// ---------------------------------------------------------------------------
// k_prep: split weights into bf16 hi/lo, transposed: dst[n*KP + k] = W[k][n]
// ---------------------------------------------------------------------------
__global__ void k_prep(const float* __restrict__ W_in, const float* __restrict__ W_rel,
                       const float* __restrict__ W_self, const float* __restrict__ W_out) {
    int b = blockIdx.x;
    const float* src = (b == 0) ? W_in
                     : (b <= 8) ? W_rel + (size_t)(b - 1) * 16384
                     : (b == 9) ? W_self : W_out;
    __nv_bfloat16* dhi = g_whi + (size_t)b * 128 * KP;
    __nv_bfloat16* dlo = g_wlo + (size_t)b * 128 * KP;
    for (int idx = threadIdx.x; idx < 16384; idx += 256) {
        int n = idx >> 7, k = idx & 127;
        float v = src[k * 128 + n];
        __nv_bfloat16 hb = __float2bfloat16_rn(v);
        dhi[n * KP + k] = hb;
        dlo[n * KP + k] = __float2bfloat16_rn(v - __bfloat162float(hb));
    }
}

// ---------------------------------------------------------------------------
// Unified tensor-core GEMM kernel. 256 threads, 64-row x 128-col tile.
// 8 warps in 4x2 grid: warp (w&3, w>>2) owns rows 16*(w&3).., cols 64*(w>>2)..
// modes: 0: h=relu(x@W_in+b)       1: scatter (w*h[src])@W_r -> relout
//        2: h2=relu(h@W_self+b+relout)   3: out=h2@W_out+b
// SMEM: Whi(34816) Wlo(34816) Ahi(17408) Alo(17408) = 104448 B -> 2 CTA/SM.
// Acc staged through smem (reusing Whi region) for coalesced epilogue.
// ---------------------------------------------------------------------------
__global__ void __launch_bounds__(256, 2)
k_gemm(int mode, int wslot,
       const float* __restrict__ Aext, const float* __restrict__ bias,
       const int* __restrict__ esrc, const int* __restrict__ edst,
       const float* __restrict__ ew, float* __restrict__ dext) {
    extern __shared__ char sm[];
    __nv_bfloat16* sWhi = (__nv_bfloat16*)sm;             // 34816 B
    __nv_bfloat16* sWlo = (__nv_bfloat16*)(sm + 34816);   // 34816 B
    __nv_bfloat16* sAhi = (__nv_bfloat16*)(sm + 69632);   // 17408 B
    __nv_bfloat16* sAlo = (__nv_bfloat16*)(sm + 87040);   // 17408 B
    float* sOut = (float*)sm;                             // 64x132 fp32 (reuse)
    __shared__ int sDst[64];

    const int tid = threadIdx.x;

    // stage weights (pre-split, pre-transposed)
    {
        int ws = wslot + ((mode == 1) ? (int)blockIdx.y : 0);
        const uint4* whi = (const uint4*)(g_whi + (size_t)ws * 128 * KP);
        const uint4* wlo = (const uint4*)(g_wlo + (size_t)ws * 128 * KP);
        uint4* dhi = (uint4*)sWhi;
        uint4* dlo = (uint4*)sWlo;
        for (int i = tid; i < 2176; i += 256) {
            dhi[i] = whi[i];
            dlo[i] = wlo[i];
        }
    }

    // stage A: 4 threads per row; thread (row=tid>>2, p=tid&3) covers cols p*32..
    const int row = tid >> 2, p = tid & 3;
    const int row0 = blockIdx.x * 64;
    bool valid;
    float sc = 1.f;
    const float* arow;
    if (mode == 1) {
        int e = row0 + row;
        valid = e < NE;
        int sidx = 0;
        int dsti = 0;
        if (valid) {
            size_t eo = (size_t)blockIdx.y * NE + e;
            sidx = esrc[eo];
            sc = ew[eo];
            dsti = edst[eo];
        } else {
            sc = 0.f;
        }
        if (p == 0) sDst[row] = dsti;
        arow = g_h + (size_t)sidx * HD;
    } else {
        int gr = row0 + row;
        valid = gr < NN;
        const float* As = (mode == 0) ? Aext : (mode == 2) ? g_h : g_h2;
        arow = As + (size_t)(valid ? gr : 0) * HD;
        sc = valid ? 1.f : 0.f;
    }
    {
        const float4* a4 = (const float4*)arow + p * 8;
        uint4* dh = (uint4*)((char*)sAhi + row * (KP * 2) + p * 64);
        uint4* dl = (uint4*)((char*)sAlo + row * (KP * 2) + p * 64);
#pragma unroll
        for (int i = 0; i < 4; i++) {
            float4 v0 = a4[2 * i], v1 = a4[2 * i + 1];
            v0.x *= sc; v0.y *= sc; v0.z *= sc; v0.w *= sc;
            v1.x *= sc; v1.y *= sc; v1.z *= sc; v1.w *= sc;
            uint4 hq, lq;
            split2(v0.x, v0.y, hq.x, lq.x);
            split2(v0.z, v0.w, hq.y, lq.y);
            split2(v1.x, v1.y, hq.z, lq.z);
            split2(v1.z, v1.w, hq.w, lq.w);
            dh[i] = hq;
            dl[i] = lq;
        }
    }
    __syncthreads();

    // MMA mainloop: warp computes 16x64; 3-term hi/lo split, fp32 accum.
    const int lane = tid & 31, warp = tid >> 5;
    const int R = 16 * (warp & 3), NB = 64 * (warp >> 2);
    const int fr = lane >> 2, q2 = (lane & 3) * 2;
    float acc[8][4];
#pragma unroll
    for (int nt = 0; nt < 8; nt++)
        acc[nt][0] = acc[nt][1] = acc[nt][2] = acc[nt][3] = 0.f;

#pragma unroll
    for (int ks = 0; ks < 8; ks++) {
        const int k0 = ks * 16;
        const __nv_bfloat16* ah = sAhi + (R + fr) * KP + k0 + q2;
        const __nv_bfloat16* al = sAlo + (R + fr) * KP + k0 + q2;
        uint32_t ah0 = *(const uint32_t*)ah;
        uint32_t ah1 = *(const uint32_t*)(ah + 8 * KP);
        uint32_t ah2 = *(const uint32_t*)(ah + 8);
        uint32_t ah3 = *(const uint32_t*)(ah + 8 * KP + 8);
        uint32_t al0 = *(const uint32_t*)al;
        uint32_t al1 = *(const uint32_t*)(al + 8 * KP);
        uint32_t al2 = *(const uint32_t*)(al + 8);
        uint32_t al3 = *(const uint32_t*)(al + 8 * KP + 8);
#pragma unroll
        for (int nt = 0; nt < 8; nt++) {
            const __nv_bfloat16* bh = sWhi + (NB + nt * 8 + fr) * KP + k0 + q2;
            const __nv_bfloat16* bl = sWlo + (NB + nt * 8 + fr) * KP + k0 + q2;
            uint32_t bh0 = *(const uint32_t*)bh;
            uint32_t bh1 = *(const uint32_t*)(bh + 8);
            uint32_t bl0 = *(const uint32_t*)bl;
            uint32_t bl1 = *(const uint32_t*)(bl + 8);
            MMA16816(acc[nt], ah0, ah1, ah2, ah3, bh0, bh1);
            MMA16816(acc[nt], ah0, ah1, ah2, ah3, bl0, bl1);
            MMA16816(acc[nt], al0, al1, al2, al3, bh0, bh1);
        }
    }

    // stage accumulators to smem (64x132 fp32), then coalesced epilogue
    __syncthreads();  // weights dead; sOut may alias sWhi now
#pragma unroll
    for (int nt = 0; nt < 8; nt++) {
        int col = NB + nt * 8 + q2;
        *(float2*)&sOut[(R + fr) * 132 + col]     = make_float2(acc[nt][0], acc[nt][1]);
        *(float2*)&sOut[(R + fr + 8) * 132 + col] = make_float2(acc[nt][2], acc[nt][3]);
    }
    __syncthreads();

    // epilogue: thread (row, p) handles cols p*32..p*32+31 of its row
    const float* srow = sOut + row * 132 + p * 32;
    if (mode == 1) {
        if (row0 + row < NE) {
            int d = sDst[row];
            float* op = g_relout + (size_t)d * HD + p * 32;
#pragma unroll
            for (int i = 0; i < 8; i++) {
                float4 v = *(const float4*)(srow + i * 4);
                asm volatile("red.global.add.v4.f32 [%0], {%1,%2,%3,%4};"
                             :: "l"(op + i * 4), "f"(v.x), "f"(v.y), "f"(v.z), "f"(v.w)
                             : "memory");
            }
        }
    } else {
        int gr = row0 + row;
        if (gr < NN) {
            const float4* b4 = (const float4*)(bias + p * 32);
            float4* o4 = (mode == 0) ? (float4*)(g_h  + (size_t)gr * HD + p * 32)
                       : (mode == 2) ? (float4*)(g_h2 + (size_t)gr * HD + p * 32)
                                     : (float4*)(dext + (size_t)gr * HD + p * 32);
            const float4* ro4 = (const float4*)(g_relout + (size_t)gr * HD + p * 32);
#pragma unroll
            for (int i = 0; i < 8; i++) {
                float4 v = *(const float4*)(srow + i * 4);
                float4 bb = b4[i];
                v.x += bb.x; v.y += bb.y; v.z += bb.z; v.w += bb.w;
                if (mode == 2) {
                    float4 rr = ro4[i];
                    v.x += rr.x; v.y += rr.y; v.z += rr.z; v.w += rr.w;
                }
                if (mode != 3) {
                    v.x = fmaxf(v.x, 0.f); v.y = fmaxf(v.y, 0.f);
                    v.z = fmaxf(v.z, 0.f); v.w = fmaxf(v.w, 0.f);
                }
                o4[i] = v;
            }
        }
    }
}

// ---------------------------------------------------------------------------
extern "C" void kernel_launch(void* const* d_in, const int* in_sizes, int n_in,
                              void* d_out, int out_size) {
    const float* x      = (const float*)d_in[0];
    const int*   esrc   = (const int*)d_in[1];
    const int*   edst   = (const int*)d_in[2];
    const float* ew     = (const float*)d_in[3];
    const float* W_in   = (const float*)d_in[4];
    const float* b_in   = (const float*)d_in[5];
    const float* W_rel  = (const float*)d_in[6];
    const float* W_self = (const float*)d_in[7];
    const float* b_self = (const float*)d_in[8];
    const float* W_out  = (const float*)d_in[9];
    const float* b_out  = (const float*)d_in[10];
    float* out = (float*)d_out;

    const int SMEM = 104448;  // Whi+Wlo+Ahi+Alo

    static bool s_init = false;
    if (!s_init) {
        cudaFuncSetAttribute(k_gemm, cudaFuncAttributeMaxDynamicSharedMemorySize, SMEM);
        s_init = true;
    }

    // 0) weight split + transpose (tiny)
    k_prep<<<11, 256>>>(W_in, W_rel, W_self, W_out);

    // 1) zero rel_out
    k_zero<<<12500, 256>>>();

    // 2) h = relu(x @ W_in + b_in)
    k_gemm<<<1563, 256, SMEM>>>(0, 0, x, b_in, nullptr, nullptr, nullptr, nullptr);

    // 3) rel_out += (w*h[src]) @ W_rel[r]  scatter, all relations
    k_gemm<<<dim3(1172, NR), 256, SMEM>>>(1, 1, nullptr, nullptr, esrc, edst, ew, nullptr);

    // 4) h2 = relu(h @ W_self + b_self + rel_out)
    k_gemm<<<1563, 256, SMEM>>>(2, 9, nullptr, b_self, nullptr, nullptr, nullptr, nullptr);

    // 5) out = h2 @ W_out + b_out
    k_gemm<<<1563, 256, SMEM>>>(3, 10, nullptr, b_out, nullptr, nullptr, nullptr, out);
}